// round 16
// baseline (speedup 1.0000x reference)
#include <cuda_runtime.h>

#define IMG_H 100
#define IMG_W 100
#define IMG_C 256
#define OUT_HW 7
#define CELLS 49

// 256-bit image load via read-only (nc) path
__device__ __forceinline__ void ldg256(const float* p, float4* d) {
    unsigned r0, r1, r2, r3, r4, r5, r6, r7;
    asm volatile("ld.global.nc.v8.b32 {%0,%1,%2,%3,%4,%5,%6,%7}, [%8];"
                 : "=r"(r0), "=r"(r1), "=r"(r2), "=r"(r3),
                   "=r"(r4), "=r"(r5), "=r"(r6), "=r"(r7) : "l"(p));
    d[0] = make_float4(__uint_as_float(r0), __uint_as_float(r1),
                       __uint_as_float(r2), __uint_as_float(r3));
    d[1] = make_float4(__uint_as_float(r4), __uint_as_float(r5),
                       __uint_as_float(r6), __uint_as_float(r7));
}

// Persistent grid-stride, cell-per-warp. Each warp loops over cells
// gw, gw+stride, ...; the roi record of the NEXT cell is prefetched while the
// current cell's corner loads are in flight, so the dependent roi-load epoch
// vanishes from the critical path.
__global__ void __launch_bounds__(256, 6)
roi_kernel(const float* __restrict__ img,
           const float* __restrict__ rois,
           float* __restrict__ out,
           int n_cells)
{
    int gw     = blockIdx.x * 8 + (threadIdx.x >> 5);
    int lane   = threadIdx.x & 31;
    int ch     = lane * 8;
    int stride = gridDim.x * 8;

    int cell = gw;
    if (cell >= n_cells) return;

    // load roi record for first cell
    float rb, rx1, ry1, rx2, ry2;
    {
        const float* r = rois + (cell / CELLS) * 5;
        rb  = __ldg(r + 0);
        rx1 = __ldg(r + 1);
        ry1 = __ldg(r + 2);
        rx2 = __ldg(r + 3);
        ry2 = __ldg(r + 4);
    }

    while (true) {
        int next = cell + stride;

        // ---- geometry for current cell (exact reference math) ----
        int rem = cell % CELLS;
        int oy  = rem / OUT_HW;
        int ox  = rem - oy * OUT_HW;
        int b   = (int)rb;

        float x1 = rx1 * (1.0f / IMG_W);
        float x2 = rx2 * (1.0f / IMG_W);
        float y1 = ry1 * (1.0f / IMG_H);
        float y2 = ry2 * (1.0f / IMG_H);

        float in_y = y1 * (float)(IMG_H - 1)
                   + (float)oy * ((y2 - y1) * (float)(IMG_H - 1) / (float)(OUT_HW - 1));
        float in_x = x1 * (float)(IMG_W - 1)
                   + (float)ox * ((x2 - x1) * (float)(IMG_W - 1) / (float)(OUT_HW - 1));

        bool valid = (in_y >= 0.0f) && (in_y <= (float)(IMG_H - 1)) &&
                     (in_x >= 0.0f) && (in_x <= (float)(IMG_W - 1));

        float fy = floorf(in_y);
        float fx = floorf(in_x);
        float ly = in_y - fy;
        float lx = in_x - fx;

        int ty = min(max((int)fy, 0), IMG_H - 1);
        int by = min(max((int)ceilf(in_y), 0), IMG_H - 1);
        int tx = min(max((int)fx, 0), IMG_W - 1);
        int bx = min(max((int)ceilf(in_x), 0), IMG_W - 1);

        int row_t = (b * IMG_H + ty) * IMG_W;
        int row_b = (b * IMG_H + by) * IMG_W;

        const float* p_tl = img + (size_t)(row_t + tx) * IMG_C + ch;
        const float* p_tr = img + (size_t)(row_t + bx) * IMG_C + ch;
        const float* p_bl = img + (size_t)(row_b + tx) * IMG_C + ch;
        const float* p_br = img + (size_t)(row_b + bx) * IMG_C + ch;

        // ---- issue corner loads (4 independent LDG.256) ----
        float4 tl[2], tr[2], bl[2], br[2];
        ldg256(p_tl, tl);
        ldg256(p_tr, tr);
        ldg256(p_bl, bl);
        ldg256(p_br, br);

        // ---- prefetch next cell's roi while corners are in flight ----
        float nb = rb, nx1 = rx1, ny1 = ry1, nx2 = rx2, ny2 = ry2;
        if (next < n_cells) {
            const float* r = rois + (next / CELLS) * 5;
            nb  = __ldg(r + 0);
            nx1 = __ldg(r + 1);
            ny1 = __ldg(r + 2);
            nx2 = __ldg(r + 3);
            ny2 = __ldg(r + 4);
        }

        // ---- lerp + store ----
        float* ocell = out + (size_t)cell * IMG_C + ch;
        if (valid) {
            float4 res[2];
            #pragma unroll
            for (int h = 0; h < 2; h++) {
                float top, bot;
                top = tl[h].x + (tr[h].x - tl[h].x) * lx;
                bot = bl[h].x + (br[h].x - bl[h].x) * lx;
                res[h].x = top + (bot - top) * ly;
                top = tl[h].y + (tr[h].y - tl[h].y) * lx;
                bot = bl[h].y + (br[h].y - bl[h].y) * lx;
                res[h].y = top + (bot - top) * ly;
                top = tl[h].z + (tr[h].z - tl[h].z) * lx;
                bot = bl[h].z + (br[h].z - bl[h].z) * lx;
                res[h].z = top + (bot - top) * ly;
                top = tl[h].w + (tr[h].w - tl[h].w) * lx;
                bot = bl[h].w + (br[h].w - bl[h].w) * lx;
                res[h].w = top + (bot - top) * ly;
            }
            __stcs((float4*)ocell, res[0]);
            __stcs((float4*)ocell + 1, res[1]);
        } else {
            float4 z = make_float4(0.f, 0.f, 0.f, 0.f);
            __stcs((float4*)ocell, z);
            __stcs((float4*)ocell + 1, z);
        }

        if (next >= n_cells) break;
        cell = next;
        rb = nb; rx1 = nx1; ry1 = ny1; rx2 = nx2; ry2 = ny2;
    }
}

extern "C" void kernel_launch(void* const* d_in, const int* in_sizes, int n_in,
                              void* d_out, int out_size)
{
    const float* img  = (const float*)d_in[0];
    const float* rois = (const float*)d_in[1];
    float* out = (float*)d_out;

    int n_rois  = in_sizes[1] / 5;                  // 2000
    int n_cells = n_rois * CELLS;                   // 98000

    // persistent-ish grid: ~6 blocks/SM on 148 SMs
    int grid = 148 * 8;
    roi_kernel<<<grid, 256>>>(img, rois, out, n_cells);
}

// round 17
// speedup vs baseline: 1.3616x; 1.3616x over previous
#include <cuda_runtime.h>

#define IMG_H 100
#define IMG_W 100
#define IMG_C 256
#define OUT_HW 7

// 256-bit image load, evict_last hint (legal v8 form on sm_103)
__device__ __forceinline__ void ldg256(const float* p, float4* d) {
    unsigned r0, r1, r2, r3, r4, r5, r6, r7;
    asm volatile("ld.global.nc.L2::evict_last.v8.b32 {%0,%1,%2,%3,%4,%5,%6,%7}, [%8];"
                 : "=r"(r0), "=r"(r1), "=r"(r2), "=r"(r3),
                   "=r"(r4), "=r"(r5), "=r"(r6), "=r"(r7) : "l"(p));
    d[0] = make_float4(__uint_as_float(r0), __uint_as_float(r1),
                       __uint_as_float(r2), __uint_as_float(r3));
    d[1] = make_float4(__uint_as_float(r4), __uint_as_float(r5),
                       __uint_as_float(r6), __uint_as_float(r7));
}
// 256-bit output store, evict_first (one STG.256 instead of two STG.128)
__device__ __forceinline__ void stg256(float* p, const float4* v) {
    asm volatile("st.global.L2::evict_first.v8.b32 [%0], {%1,%2,%3,%4,%5,%6,%7,%8};"
                 :: "l"(p),
                    "r"(__float_as_uint(v[0].x)), "r"(__float_as_uint(v[0].y)),
                    "r"(__float_as_uint(v[0].z)), "r"(__float_as_uint(v[0].w)),
                    "r"(__float_as_uint(v[1].x)), "r"(__float_as_uint(v[1].y)),
                    "r"(__float_as_uint(v[1].z)), "r"(__float_as_uint(v[1].w))
                 : "memory");
}

// One-shot: 256-thread block = 8 output cells, 32 lanes/cell, 8 ch/lane.
// 4 independent LDG.256 per thread; proven structure at the LTS roofline.
__global__ void __launch_bounds__(256, 8)
roi_crop_resize_kernel(const float* __restrict__ img,
                       const float* __restrict__ rois,
                       float* __restrict__ out,
                       int n_cells)
{
    int cell = blockIdx.x * 8 + (threadIdx.x >> 5);
    if (cell >= n_cells) return;
    int lane = threadIdx.x & 31;

    int ox  = cell % OUT_HW;
    int oy  = (cell / OUT_HW) % OUT_HW;
    int roi = cell / (OUT_HW * OUT_HW);

    const float* r = rois + roi * 5;
    float rb  = __ldg(r + 0);
    float rx1 = __ldg(r + 1);
    float ry1 = __ldg(r + 2);
    float rx2 = __ldg(r + 3);
    float ry2 = __ldg(r + 4);

    int b = (int)rb;

    // normalized coords exactly as reference: b[:,k] = roi[:,k]/scale
    float x1 = rx1 * (1.0f / IMG_W);
    float x2 = rx2 * (1.0f / IMG_W);
    float y1 = ry1 * (1.0f / IMG_H);
    float y2 = ry2 * (1.0f / IMG_H);

    // in_y = y1*(H-1) + oy * ((y2-y1)*(H-1)/(ch-1))
    float in_y = y1 * (float)(IMG_H - 1)
               + (float)oy * ((y2 - y1) * (float)(IMG_H - 1) / (float)(OUT_HW - 1));
    float in_x = x1 * (float)(IMG_W - 1)
               + (float)ox * ((x2 - x1) * (float)(IMG_W - 1) / (float)(OUT_HW - 1));

    int ch = lane * 8;
    float* ocell = out + (size_t)cell * IMG_C + ch;

    bool valid = (in_y >= 0.0f) && (in_y <= (float)(IMG_H - 1)) &&
                 (in_x >= 0.0f) && (in_x <= (float)(IMG_W - 1));
    if (!valid) {
        float4 z[2];
        z[0] = z[1] = make_float4(0.f, 0.f, 0.f, 0.f);
        stg256(ocell, z);
        return;
    }

    float fy = floorf(in_y);
    float fx = floorf(in_x);
    float ly = in_y - fy;
    float lx = in_x - fx;

    int ty = min(max((int)fy, 0), IMG_H - 1);
    int by = min(max((int)ceilf(in_y), 0), IMG_H - 1);
    int tx = min(max((int)fx, 0), IMG_W - 1);
    int bx = min(max((int)ceilf(in_x), 0), IMG_W - 1);

    int row_t = (b * IMG_H + ty) * IMG_W;
    int row_b = (b * IMG_H + by) * IMG_W;

    const float* p_tl = img + (size_t)(row_t + tx) * IMG_C + ch;
    const float* p_tr = img + (size_t)(row_t + bx) * IMG_C + ch;
    const float* p_bl = img + (size_t)(row_b + tx) * IMG_C + ch;
    const float* p_br = img + (size_t)(row_b + bx) * IMG_C + ch;

    // 4 independent 256-bit loads in flight
    float4 tl[2], tr[2], bl[2], br[2];
    ldg256(p_tl, tl);
    ldg256(p_tr, tr);
    ldg256(p_bl, bl);
    ldg256(p_br, br);

    // lerp exactly as reference: top = tl + (tr-tl)*lx; out = top + (bot-top)*ly
    float4 res[2];
    #pragma unroll
    for (int h = 0; h < 2; h++) {
        float top, bot;
        top = tl[h].x + (tr[h].x - tl[h].x) * lx;
        bot = bl[h].x + (br[h].x - bl[h].x) * lx;
        res[h].x = top + (bot - top) * ly;
        top = tl[h].y + (tr[h].y - tl[h].y) * lx;
        bot = bl[h].y + (br[h].y - bl[h].y) * lx;
        res[h].y = top + (bot - top) * ly;
        top = tl[h].z + (tr[h].z - tl[h].z) * lx;
        bot = bl[h].z + (br[h].z - bl[h].z) * lx;
        res[h].z = top + (bot - top) * ly;
        top = tl[h].w + (tr[h].w - tl[h].w) * lx;
        bot = bl[h].w + (br[h].w - bl[h].w) * lx;
        res[h].w = top + (bot - top) * ly;
    }

    stg256(ocell, res);
}

extern "C" void kernel_launch(void* const* d_in, const int* in_sizes, int n_in,
                              void* d_out, int out_size)
{
    const float* img  = (const float*)d_in[0];
    const float* rois = (const float*)d_in[1];
    float* out = (float*)d_out;

    int n_rois  = in_sizes[1] / 5;                  // 2000
    int n_cells = n_rois * OUT_HW * OUT_HW;         // 98000

    int grid = (n_cells + 7) / 8;                   // 8 cells per 256-thread block
    roi_crop_resize_kernel<<<grid, 256>>>(img, rois, out, n_cells);
}